// round 2
// baseline (speedup 1.0000x reference)
#include <cuda_runtime.h>
#include <cstdint>

// Problem constants (reference: D=128, T=17, N=87381)
#define DD 128
#define TMAXTAGS 32
#define CAP 87424   // per-tag index capacity (>= N, fully safe)

// Scratch (static device globals; no cudaMalloc allowed)
__device__ int g_count[TMAXTAGS];
__device__ int g_idx[TMAXTAGS * CAP];

// ---------------------------------------------------------------------------
// Kernel 1: init output (relu>=0 so 0 is the max-identity) and tag counters
// ---------------------------------------------------------------------------
__global__ void init_kernel(float* __restrict__ out, int T) {
    int i = threadIdx.x;
    if (i < DD) out[i] = 0.0f;
    if (i < T) g_count[i] = 0;
}

// ---------------------------------------------------------------------------
// Kernel 2: bucket node indices by tag (order nondeterministic; final result
// is an exact elementwise max over a fixed set -> deterministic output)
// ---------------------------------------------------------------------------
__global__ void compact_kernel(const int* __restrict__ tag, int N) {
    int n = blockIdx.x * blockDim.x + threadIdx.x;
    if (n < N) {
        int t = tag[n];
        int p = atomicAdd(&g_count[t], 1);
        g_idx[t * CAP + p] = n;
    }
}

// ---------------------------------------------------------------------------
// Kernel 3: per-tag GEMM + relu + running max.
// grid = (G, T). Block: 128 threads, tile = 64 nodes x 128 outputs, K=128.
// Thread (mG = tid>>4 in 0..7, nG = tid&15 in 0..15) owns an 8x8 register
// tile: nodes m = mG + 8s, outputs i = nG + 16r. Strided ownership makes
// quarter-warp float4 smem loads hit distinct bank-quads (stride 132 pad).
// ---------------------------------------------------------------------------
#define SSTRIDE 132                    // 128 + 4 floats pad (16B-aligned rows)
#define SMEM_FLOATS (128 * SSTRIDE + 64 * SSTRIDE + 128 + 128)
#define SMEM_BYTES  (SMEM_FLOATS * 4 + 64 * 4)

extern __shared__ float s_buf[];

__global__ __launch_bounds__(128, 2) void gemm_max_kernel(
    const float* __restrict__ emb, const float* __restrict__ W,
    const float* __restrict__ b, float* __restrict__ out, int G)
{
    const int t   = blockIdx.y;
    const int tid = threadIdx.x;
    const int cnt = g_count[t];

    float* Ws   = s_buf;                       // [128][132]
    float* Es   = Ws + 128 * SSTRIDE;          // [64][132]
    float* bs   = Es + 64 * SSTRIDE;           // [128]
    float* bmax = bs + 128;                    // [128]
    int*   sIdx = (int*)(bmax + 128);          // [64]

    if ((long)blockIdx.x * 64 >= cnt) return;  // uniform across block

    bmax[tid] = 0.0f;

    // Load W[t] into smem transpose-free ([i][k], k-contiguous), coalesced.
    const float* Wt = W + (size_t)t * DD * DD;
    #pragma unroll
    for (int j = 0; j < 32; j++) {
        int c  = tid + j * 128;        // float4 chunk id, 0..4095
        int i  = c >> 5;
        int k4 = c & 31;
        float4 v = *(const float4*)(Wt + i * DD + k4 * 4);
        *(float4*)(Ws + i * SSTRIDE + k4 * 4) = v;
    }
    bs[tid] = b[t * DD + tid];

    const int mG = tid >> 4;   // 0..7
    const int nG = tid & 15;   // 0..15

    __syncthreads();

    for (int tile = blockIdx.x; tile * 64 < cnt; tile += G) {
        const int base = tile * 64;
        if (tid < 64) {
            int p = base + tid;
            sIdx[tid] = (p < cnt) ? g_idx[t * CAP + p] : 0;  // clamp; masked later
        }
        __syncthreads();

        // Gather 64 emb rows (coalesced: each warp streams one 512B row chunk)
        #pragma unroll
        for (int j = 0; j < 16; j++) {
            int c  = tid + j * 128;    // 0..2047
            int m  = c >> 5;
            int k4 = c & 31;
            const float* src = emb + (size_t)sIdx[m] * DD + k4 * 4;
            *(float4*)(Es + m * SSTRIDE + k4 * 4) = *(const float4*)src;
        }
        __syncthreads();

        float acc[8][8];
        #pragma unroll
        for (int s = 0; s < 8; s++)
            #pragma unroll
            for (int r = 0; r < 8; r++) acc[s][r] = 0.0f;

        #pragma unroll 2
        for (int k4 = 0; k4 < 32; k4++) {
            float4 ev[8], wv[8];
            #pragma unroll
            for (int s = 0; s < 8; s++)
                ev[s] = *(float4*)(Es + (mG + 8 * s) * SSTRIDE + k4 * 4);
            #pragma unroll
            for (int r = 0; r < 8; r++)
                wv[r] = *(float4*)(Ws + (nG + 16 * r) * SSTRIDE + k4 * 4);
            #pragma unroll
            for (int s = 0; s < 8; s++)
                #pragma unroll
                for (int r = 0; r < 8; r++) {
                    acc[s][r] = fmaf(ev[s].x, wv[r].x, acc[s][r]);
                    acc[s][r] = fmaf(ev[s].y, wv[r].y, acc[s][r]);
                    acc[s][r] = fmaf(ev[s].z, wv[r].z, acc[s][r]);
                    acc[s][r] = fmaf(ev[s].w, wv[r].w, acc[s][r]);
                }
        }

        // Epilogue: bias + relu + masked max into block accumulator.
        // relu output >= 0, so int-bit atomicMax == float max.
        #pragma unroll
        for (int s = 0; s < 8; s++) {
            int m = mG + 8 * s;
            if (base + m < cnt) {
                #pragma unroll
                for (int r = 0; r < 8; r++) {
                    int i = nG + 16 * r;
                    float y = fmaxf(acc[s][r] + bs[i], 0.0f);
                    atomicMax((int*)&bmax[i], __float_as_int(y));
                }
            }
        }
        __syncthreads();  // protect Es/sIdx reuse; also orders bmax for publish
    }

    atomicMax((int*)out + tid, __float_as_int(bmax[tid]));
}

// ---------------------------------------------------------------------------
// Launch
// ---------------------------------------------------------------------------
extern "C" void kernel_launch(void* const* d_in, const int* in_sizes, int n_in,
                              void* d_out, int out_size) {
    const float* emb = (const float*)d_in[0];
    const float* W   = (const float*)d_in[1];
    const float* b   = (const float*)d_in[2];
    const int*   tag = (const int*)d_in[3];
    // d_in[4] (parent) and d_in[5] (depth) are mathematically irrelevant:
    // root z == elementwise max over all nodes of relu(W[tag]@emb + b).

    float* out = (float*)d_out;
    const int N = in_sizes[3];                 // node count
    const int T = in_sizes[2] / DD;            // tag count (17)

    static bool attr_set = false;
    if (!attr_set) {
        cudaFuncSetAttribute(gemm_max_kernel,
                             cudaFuncAttributeMaxDynamicSharedMemorySize,
                             SMEM_BYTES);
        attr_set = true;
    }

    init_kernel<<<1, 128>>>(out, T);
    compact_kernel<<<(N + 255) / 256, 256>>>(tag, N);

    const int G = 96;  // tiles per tag ~81; loop covers any imbalance
    dim3 grid(G, T);
    gemm_max_kernel<<<grid, 128, SMEM_BYTES>>>(emb, W, b, out, G);
}

// round 6
// speedup vs baseline: 1.3019x; 1.3019x over previous
#include <cuda_runtime.h>
#include <cuda_bf16.h>
#include <cstdint>

// Problem constants: D=128, T=17, N=87381
#define DD 128
#define TMAXTAGS 32
#define CAP 87424
#define TILE_M 64

// Scratch (static device globals; zero-initialized at module load)
__device__ int g_count[TMAXTAGS];
__device__ int g_done[TMAXTAGS];
__device__ int g_idx[TMAXTAGS * CAP];

// ---------------------------------------------------------------------------
// PTX helpers (legacy tensor-core path: valid on plain sm_100 target)
// ---------------------------------------------------------------------------
__device__ __forceinline__ uint32_t smem_u32(const void* p) {
    uint32_t a;
    asm("{ .reg .u64 t; cvta.to.shared.u64 t, %1; cvt.u32.u64 %0, t; }"
        : "=r"(a) : "l"(p));
    return a;
}

__device__ __forceinline__ void ldsm_x4(uint32_t* r, uint32_t addr) {
    asm volatile("ldmatrix.sync.aligned.m8n8.x4.shared.b16 {%0,%1,%2,%3}, [%4];"
                 : "=r"(r[0]), "=r"(r[1]), "=r"(r[2]), "=r"(r[3]) : "r"(addr));
}
// Non-trans x2: W staged [n][k] row-major (k-contiguous) == col-major B for
// mma.row.col; lane i gets k-consecutive pair at (k=(i%4)*2, n=i/4). Correct.
__device__ __forceinline__ void ldsm_x2(uint32_t* r, uint32_t addr) {
    asm volatile("ldmatrix.sync.aligned.m8n8.x2.shared.b16 {%0,%1}, [%2];"
                 : "=r"(r[0]), "=r"(r[1]) : "r"(addr));
}
__device__ __forceinline__ void mma16816(float* d, const uint32_t* a, const uint32_t* b) {
    asm volatile(
        "mma.sync.aligned.m16n8k16.row.col.f32.bf16.bf16.f32 "
        "{%0,%1,%2,%3}, {%4,%5,%6,%7}, {%8,%9}, {%0,%1,%2,%3};"
        : "+f"(d[0]), "+f"(d[1]), "+f"(d[2]), "+f"(d[3])
        : "r"(a[0]), "r"(a[1]), "r"(a[2]), "r"(a[3]), "r"(b[0]), "r"(b[1]));
}

// ---------------------------------------------------------------------------
// Shared memory layout. Row stride 272B (128 bf16 + 8 pad): 8 consecutive
// rows land at 0,16,32,...,112 mod 128 -> ldmatrix conflict-free.
// ---------------------------------------------------------------------------
#define RSTRIDE 272
#define OFF_WHI   0                         // 128*272 = 34816
#define OFF_WLO   34816                     // 34816
#define OFF_AHI   69632                     // 64*272 = 17408
#define OFF_ALO   87040                     // 17408
#define OFF_BIAS  104448                    // 128 f32
#define OFF_WMAX  104960                    // 4*128 f32
#define OFF_SIDX  107008                    // 64 int
#define SMEM_TOTAL 107264

extern __shared__ char s_raw[];

// Convert 4 fp32 -> hi/lo bf16 pairs, store 8B each into padded tiles.
__device__ __forceinline__ void cvt_store(char* hi, char* lo, int row, int lid, float4 v) {
    __nv_bfloat16 h0 = __float2bfloat16(v.x);
    __nv_bfloat16 h1 = __float2bfloat16(v.y);
    __nv_bfloat16 h2 = __float2bfloat16(v.z);
    __nv_bfloat16 h3 = __float2bfloat16(v.w);
    __nv_bfloat16 l0 = __float2bfloat16(v.x - __bfloat162float(h0));
    __nv_bfloat16 l1 = __float2bfloat16(v.y - __bfloat162float(h1));
    __nv_bfloat16 l2 = __float2bfloat16(v.z - __bfloat162float(h2));
    __nv_bfloat16 l3 = __float2bfloat16(v.w - __bfloat162float(h3));
    uint32_t hA = ((uint32_t)__bfloat16_as_ushort(h1) << 16) | __bfloat16_as_ushort(h0);
    uint32_t hB = ((uint32_t)__bfloat16_as_ushort(h3) << 16) | __bfloat16_as_ushort(h2);
    uint32_t lA = ((uint32_t)__bfloat16_as_ushort(l1) << 16) | __bfloat16_as_ushort(l0);
    uint32_t lB = ((uint32_t)__bfloat16_as_ushort(l3) << 16) | __bfloat16_as_ushort(l2);
    uint32_t o = (uint32_t)row * RSTRIDE + (uint32_t)lid * 8;
    *(uint2*)(hi + o) = make_uint2(hA, hB);
    *(uint2*)(lo + o) = make_uint2(lA, lB);
}

// ---------------------------------------------------------------------------
// Kernel 1: zero output (block 0) + bucket node indices by tag.
// ---------------------------------------------------------------------------
__global__ void compact_kernel(const int* __restrict__ tag, int N,
                               float* __restrict__ out) {
    if (blockIdx.x == 0 && threadIdx.x < DD) out[threadIdx.x] = 0.0f;
    int n = blockIdx.x * blockDim.x + threadIdx.x;
    if (n < N) {
        int t = tag[n];
        int p = atomicAdd(&g_count[t], 1);
        g_idx[t * CAP + p] = n;
    }
}

// ---------------------------------------------------------------------------
// Kernel 2: per-tag 3-term split-bf16 HMMA GEMM + max reduce.
// grid = (G, T), 128 threads, 2 CTAs/SM. Tile = 64 nodes x 128 outs, K=128.
// ---------------------------------------------------------------------------
__global__ __launch_bounds__(128, 2) void gemm_max_kernel(
    const float* __restrict__ emb, const float* __restrict__ W,
    const float* __restrict__ b, float* __restrict__ out, int G)
{
    char* smem = s_raw;
    const int t   = blockIdx.y;
    const int tid = threadIdx.x;
    const int wid = tid >> 5;
    const int lid = tid & 31;
    const int cnt = g_count[t];

    const bool active = (long)blockIdx.x * TILE_M < cnt;  // block-uniform
    if (active) {
        const uint32_t sb = smem_u32(smem);

        // --- Prologue: convert W[t] into Whi/Wlo, stage bias ---
        const float* Wt = W + (size_t)t * DD * DD;
        for (int r = wid; r < DD; r += 4) {
            float4 v = *(const float4*)(Wt + r * DD + lid * 4);
            cvt_store(smem + OFF_WHI, smem + OFF_WLO, r, lid, v);
        }
        ((float*)(smem + OFF_BIAS))[tid] = b[t * DD + tid];

        // ldmatrix per-thread offsets
        // A (x4): lanes 0-7 rows m0..7 k-half 0 | 8-15 rows m8..15 k-half 0
        //         16-23 rows m0..7 k-half 1    | 24-31 rows m8..15 k-half 1
        const uint32_t offA = (uint32_t)(wid * 16 + (lid & 15)) * RSTRIDE
                            + (uint32_t)(lid >> 4) * 16;
        // B (x2, non-trans): lanes 0-7 rows n0..7 (k0-7) | 8-15 rows n0..7 (k8-15)
        const int l2 = lid & 15;
        const uint32_t offB = (uint32_t)(l2 & 7) * RSTRIDE
                            + (uint32_t)((l2 >> 3) & 1) * 16;

        const uint32_t aHi = sb + OFF_AHI + offA, aLo = sb + OFF_ALO + offA;
        const uint32_t bHi = sb + OFF_WHI + offB, bLo = sb + OFF_WLO + offB;

        float mx[64];
        #pragma unroll
        for (int i = 0; i < 64; i++) mx[i] = __int_as_float(0xff800000);

        int* sIdx = (int*)(smem + OFF_SIDX);
        __syncthreads();

        for (int tile = blockIdx.x; tile * TILE_M < cnt; tile += G) {
            const int base = tile * TILE_M;
            if (tid < TILE_M) {
                int p = base + tid;
                sIdx[tid] = (p < cnt) ? g_idx[t * CAP + p] : g_idx[t * CAP];
            }
            __syncthreads();

            // Gather + convert 64 emb rows (coalesced 512B per warp per row)
            for (int r = wid; r < TILE_M; r += 4) {
                float4 v = *(const float4*)(emb + (size_t)sIdx[r] * DD + lid * 4);
                cvt_store(smem + OFF_AHI, smem + OFF_ALO, r, lid, v);
            }
            __syncthreads();

            float acc[64];
            #pragma unroll
            for (int i = 0; i < 64; i++) acc[i] = 0.0f;

            // 3-term split GEMM with fragment reuse:
            // D += Ahi*Whi + Ahi*Wlo + Alo*Whi  (lo*lo dropped, ~4e-6 rel)
            #pragma unroll
            for (int kk = 0; kk < 8; kk++) {
                uint32_t ah[4], al[4];
                ldsm_x4(ah, aHi + kk * 32);
                ldsm_x4(al, aLo + kk * 32);
                #pragma unroll
                for (int j = 0; j < 16; j++) {
                    uint32_t bh[2], bl[2];
                    ldsm_x2(bh, bHi + (uint32_t)j * (8 * RSTRIDE) + kk * 32);
                    ldsm_x2(bl, bLo + (uint32_t)j * (8 * RSTRIDE) + kk * 32);
                    mma16816(&acc[j * 4], ah, bh);
                    mma16816(&acc[j * 4], ah, bl);
                    mma16816(&acc[j * 4], al, bh);
                }
            }

            // Masked running max (fragment rows g=lid>>2 and g+8)
            const int rowb = base + wid * 16 + (lid >> 2);
            const bool v0 = rowb < cnt;
            const bool v1 = rowb + 8 < cnt;
            #pragma unroll
            for (int j = 0; j < 16; j++) {
                if (v0) {
                    mx[j*4+0] = fmaxf(mx[j*4+0], acc[j*4+0]);
                    mx[j*4+1] = fmaxf(mx[j*4+1], acc[j*4+1]);
                }
                if (v1) {
                    mx[j*4+2] = fmaxf(mx[j*4+2], acc[j*4+2]);
                    mx[j*4+3] = fmaxf(mx[j*4+3], acc[j*4+3]);
                }
            }
            __syncthreads();   // A/sIdx fully consumed before next overwrite
        }

        // --- Reduce: fragment rows, then lanes sharing lid&3 (same cols) ---
        float* wm = (float*)(smem + OFF_WMAX) + wid * 128;
        const int q = lid & 3;
        #pragma unroll
        for (int j = 0; j < 16; j++) {
            float v0 = fmaxf(mx[j*4+0], mx[j*4+2]);
            float v1 = fmaxf(mx[j*4+1], mx[j*4+3]);
            #pragma unroll
            for (int s = 4; s < 32; s <<= 1) {
                v0 = fmaxf(v0, __shfl_xor_sync(0xFFFFFFFFu, v0, s));
                v1 = fmaxf(v1, __shfl_xor_sync(0xFFFFFFFFu, v1, s));
            }
            if (lid < 4) {
                wm[j * 8 + q * 2 + 0] = v0;
                wm[j * 8 + q * 2 + 1] = v1;
            }
        }
        __syncthreads();

        {
            float* wmax = (float*)(smem + OFF_WMAX);
            float m = fmaxf(fmaxf(wmax[tid], wmax[128 + tid]),
                            fmaxf(wmax[256 + tid], wmax[384 + tid]));
            float bias = ((float*)(smem + OFF_BIAS))[tid];
            float y = fmaxf(m + bias, 0.0f);   // >=0 -> int-bit atomicMax valid
            atomicMax((int*)out + tid, __float_as_int(y));
        }
    }

    // End ticket: last block of this tag resets counters for the next replay.
    if (tid == 0) {
        __threadfence();
        int v = atomicAdd(&g_done[t], 1);
        if (v == (int)gridDim.x - 1) {
            g_done[t] = 0;
            g_count[t] = 0;
        }
    }
}

// ---------------------------------------------------------------------------
// Launch
// ---------------------------------------------------------------------------
extern "C" void kernel_launch(void* const* d_in, const int* in_sizes, int n_in,
                              void* d_out, int out_size) {
    const float* emb = (const float*)d_in[0];
    const float* W   = (const float*)d_in[1];
    const float* b   = (const float*)d_in[2];
    const int*   tag = (const int*)d_in[3];
    // parent/depth irrelevant: root z == elementwise max over all nodes of
    // relu(W[tag] @ emb + b); relu>=0 makes 0 the max identity.

    float* out = (float*)d_out;
    const int N = in_sizes[3];
    const int T = in_sizes[2] / DD;

    static bool attr_set = false;
    if (!attr_set) {
        cudaFuncSetAttribute(gemm_max_kernel,
                             cudaFuncAttributeMaxDynamicSharedMemorySize,
                             SMEM_TOTAL);
        attr_set = true;
    }

    compact_kernel<<<(N + 255) / 256, 256>>>(tag, N, out);

    const int G = 18;  // 18*17 = 306 blocks ~ 2 waves of 148 SMs @ 2 CTA/SM
    dim3 grid(G, T);
    gemm_max_kernel<<<grid, 128, SMEM_TOTAL>>>(emb, W, b, out, G);
}

// round 7
// speedup vs baseline: 1.9989x; 1.5354x over previous
#include <cuda_runtime.h>
#include <cuda_bf16.h>
#include <cstdint>

// Problem constants: D=128, T=17, N=87381
#define DD 128
#define TMAXTAGS 32
#define CAP 87424
#define TILE_M 64

// Scratch (static device globals; zero-initialized at module load)
__device__ int g_count[TMAXTAGS];
__device__ int g_done[TMAXTAGS];
__device__ int g_idx[TMAXTAGS * CAP];

// ---------------------------------------------------------------------------
// PTX helpers (legacy tensor-core path: valid on plain sm_100 target)
// ---------------------------------------------------------------------------
__device__ __forceinline__ uint32_t smem_u32(const void* p) {
    uint32_t a;
    asm("{ .reg .u64 t; cvta.to.shared.u64 t, %1; cvt.u32.u64 %0, t; }"
        : "=r"(a) : "l"(p));
    return a;
}

__device__ __forceinline__ void ldsm_x4(uint32_t* r, uint32_t addr) {
    asm volatile("ldmatrix.sync.aligned.m8n8.x4.shared.b16 {%0,%1,%2,%3}, [%4];"
                 : "=r"(r[0]), "=r"(r[1]), "=r"(r[2]), "=r"(r[3]) : "r"(addr));
}
__device__ __forceinline__ void mma16816(float* d, const uint32_t* a, const uint32_t* b) {
    asm volatile(
        "mma.sync.aligned.m16n8k16.row.col.f32.bf16.bf16.f32 "
        "{%0,%1,%2,%3}, {%4,%5,%6,%7}, {%8,%9}, {%0,%1,%2,%3};"
        : "+f"(d[0]), "+f"(d[1]), "+f"(d[2]), "+f"(d[3])
        : "r"(a[0]), "r"(a[1]), "r"(a[2]), "r"(a[3]), "r"(b[0]), "r"(b[1]));
}

// ---------------------------------------------------------------------------
// Shared memory layout. Row stride 272B (128 bf16 + 8 pad): within every
// quarter-warp ldmatrix phase (8 lanes, 16B each), the 8 addressed rows hit
// distinct 16B bank-quads (16*r mod 128 distinct for r in any 8-row run).
// ---------------------------------------------------------------------------
#define RSTRIDE 272
#define OFF_WHI   0                         // 128*272 = 34816
#define OFF_WLO   34816                     // 34816
#define OFF_AHI   69632                     // 64*272 = 17408
#define OFF_ALO   87040                     // 17408
#define OFF_BIAS  104448                    // 128 f32
#define OFF_WMAX  104960                    // 8*64 f32 = 2048B
#define OFF_SIDX  107008                    // 64 int
#define SMEM_TOTAL 107264

extern __shared__ char s_raw[];

// Convert 4 fp32 -> hi/lo bf16 pairs, store 8B each into padded tiles.
__device__ __forceinline__ void cvt_store(char* hi, char* lo, int row, int lid, float4 v) {
    __nv_bfloat16 h0 = __float2bfloat16(v.x);
    __nv_bfloat16 h1 = __float2bfloat16(v.y);
    __nv_bfloat16 h2 = __float2bfloat16(v.z);
    __nv_bfloat16 h3 = __float2bfloat16(v.w);
    __nv_bfloat16 l0 = __float2bfloat16(v.x - __bfloat162float(h0));
    __nv_bfloat16 l1 = __float2bfloat16(v.y - __bfloat162float(h1));
    __nv_bfloat16 l2 = __float2bfloat16(v.z - __bfloat162float(h2));
    __nv_bfloat16 l3 = __float2bfloat16(v.w - __bfloat162float(h3));
    uint32_t hA = ((uint32_t)__bfloat16_as_ushort(h1) << 16) | __bfloat16_as_ushort(h0);
    uint32_t hB = ((uint32_t)__bfloat16_as_ushort(h3) << 16) | __bfloat16_as_ushort(h2);
    uint32_t lA = ((uint32_t)__bfloat16_as_ushort(l1) << 16) | __bfloat16_as_ushort(l0);
    uint32_t lB = ((uint32_t)__bfloat16_as_ushort(l3) << 16) | __bfloat16_as_ushort(l2);
    uint32_t o = (uint32_t)row * RSTRIDE + (uint32_t)lid * 8;
    *(uint2*)(hi + o) = make_uint2(hA, hB);
    *(uint2*)(lo + o) = make_uint2(lA, lB);
}

// ---------------------------------------------------------------------------
// Kernel 1: zero output (block 0) + bucket node indices by tag.
// ---------------------------------------------------------------------------
__global__ void compact_kernel(const int* __restrict__ tag, int N,
                               float* __restrict__ out) {
    if (blockIdx.x == 0 && threadIdx.x < DD) out[threadIdx.x] = 0.0f;
    int n = blockIdx.x * blockDim.x + threadIdx.x;
    if (n < N) {
        int t = tag[n];
        int p = atomicAdd(&g_count[t], 1);
        g_idx[t * CAP + p] = n;
    }
}

// ---------------------------------------------------------------------------
// Kernel 2: per-tag 3-term split-bf16 HMMA GEMM + max reduce.
// grid = (G, T), 256 threads (8 warps), 2 CTAs/SM -> 16 warps/SM, 4/SMSP.
// Warp (rowg = wid&3, colg = wid>>2) owns 16 rows x 64 cols of the
// 64 x 128 tile: rows rowg*16.., cols colg*64 + j*8, j=0..7.
// ---------------------------------------------------------------------------
__global__ __launch_bounds__(256, 2) void gemm_max_kernel(
    const float* __restrict__ emb, const float* __restrict__ W,
    const float* __restrict__ b, float* __restrict__ out, int G)
{
    char* smem = s_raw;
    const int t   = blockIdx.y;
    const int tid = threadIdx.x;
    const int wid = tid >> 5;
    const int lid = tid & 31;
    const int cnt = g_count[t];

    const bool active = (long)blockIdx.x * TILE_M < cnt;  // block-uniform
    if (active) {
        const uint32_t sb = smem_u32(smem);
        const int rowg = wid & 3;
        const int colg = wid >> 2;

        // --- Prologue: convert W[t] into Whi/Wlo, stage bias ---
        const float* Wt = W + (size_t)t * DD * DD;
        for (int r = wid; r < DD; r += 8) {
            float4 v = *(const float4*)(Wt + r * DD + lid * 4);
            cvt_store(smem + OFF_WHI, smem + OFF_WLO, r, lid, v);
        }
        if (tid < DD) ((float*)(smem + OFF_BIAS))[tid] = b[t * DD + tid];

        // A (x4): lanes 0-15 -> 16 rows (k-half 0), 16-31 same rows k-half 1
        const uint32_t offA = (uint32_t)(rowg * 16 + (lid & 15)) * RSTRIDE
                            + (uint32_t)(lid >> 4) * 16;
        // B (x4, non-trans): matrices (n0-7,k0-7),(n0-7,k8-15),(n8-15,k0-7),
        // (n8-15,k8-15) -> fragments for n-tiles j and j+1 in one ldmatrix.
        const uint32_t offB = (uint32_t)((lid & 7) + ((lid >> 4) << 3)) * RSTRIDE
                            + (uint32_t)((lid >> 3) & 1) * 16
                            + (uint32_t)(colg * 64) * RSTRIDE;

        const uint32_t aHi = sb + OFF_AHI + offA, aLo = sb + OFF_ALO + offA;
        const uint32_t bHi = sb + OFF_WHI + offB, bLo = sb + OFF_WLO + offB;

        float mx[32];
        #pragma unroll
        for (int i = 0; i < 32; i++) mx[i] = __int_as_float(0xff800000);

        int* sIdx = (int*)(smem + OFF_SIDX);
        __syncthreads();

        for (int tile = blockIdx.x; tile * TILE_M < cnt; tile += G) {
            const int base = tile * TILE_M;
            if (tid < TILE_M) {
                int p = base + tid;
                sIdx[tid] = (p < cnt) ? g_idx[t * CAP + p] : g_idx[t * CAP];
            }
            __syncthreads();

            // Gather + convert 64 emb rows (warp-per-row, coalesced 512B)
            for (int r = wid; r < TILE_M; r += 8) {
                float4 v = *(const float4*)(emb + (size_t)sIdx[r] * DD + lid * 4);
                cvt_store(smem + OFF_AHI, smem + OFF_ALO, r, lid, v);
            }
            __syncthreads();

            float acc[32];
            #pragma unroll
            for (int i = 0; i < 32; i++) acc[i] = 0.0f;

            // 3-term split GEMM: D += Ahi*Whi + Ahi*Wlo + Alo*Whi
            #pragma unroll
            for (int kk = 0; kk < 8; kk++) {
                uint32_t ah[4], al[4];
                ldsm_x4(ah, aHi + kk * 32);
                ldsm_x4(al, aLo + kk * 32);
                #pragma unroll
                for (int jj = 0; jj < 4; jj++) {
                    uint32_t bh[4], bl[4];
                    ldsm_x4(bh, bHi + (uint32_t)jj * (16 * RSTRIDE) + kk * 32);
                    ldsm_x4(bl, bLo + (uint32_t)jj * (16 * RSTRIDE) + kk * 32);
                    mma16816(&acc[jj * 8 + 0], ah, bh + 0);
                    mma16816(&acc[jj * 8 + 0], ah, bl + 0);
                    mma16816(&acc[jj * 8 + 0], al, bh + 0);
                    mma16816(&acc[jj * 8 + 4], ah, bh + 2);
                    mma16816(&acc[jj * 8 + 4], ah, bl + 2);
                    mma16816(&acc[jj * 8 + 4], al, bh + 2);
                }
            }

            // Masked running max (fragment rows g=lid>>2 and g+8)
            const int rowb = base + rowg * 16 + (lid >> 2);
            const bool v0 = rowb < cnt;
            const bool v1 = rowb + 8 < cnt;
            #pragma unroll
            for (int j = 0; j < 8; j++) {
                if (v0) {
                    mx[j*4+0] = fmaxf(mx[j*4+0], acc[j*4+0]);
                    mx[j*4+1] = fmaxf(mx[j*4+1], acc[j*4+1]);
                }
                if (v1) {
                    mx[j*4+2] = fmaxf(mx[j*4+2], acc[j*4+2]);
                    mx[j*4+3] = fmaxf(mx[j*4+3], acc[j*4+3]);
                }
            }
            __syncthreads();   // A/sIdx fully consumed before next overwrite
        }

        // --- Reduce: fragment rows, then lanes sharing lid&3 (same cols) ---
        float* wm = (float*)(smem + OFF_WMAX) + wid * 64;
        const int q = lid & 3;
        #pragma unroll
        for (int j = 0; j < 8; j++) {
            float v0 = fmaxf(mx[j*4+0], mx[j*4+2]);
            float v1 = fmaxf(mx[j*4+1], mx[j*4+3]);
            #pragma unroll
            for (int s = 4; s < 32; s <<= 1) {
                v0 = fmaxf(v0, __shfl_xor_sync(0xFFFFFFFFu, v0, s));
                v1 = fmaxf(v1, __shfl_xor_sync(0xFFFFFFFFu, v1, s));
            }
            if (lid < 4) {
                wm[j * 8 + q * 2 + 0] = v0;
                wm[j * 8 + q * 2 + 1] = v1;
            }
        }
        __syncthreads();

        if (tid < DD) {
            float* wall = (float*)(smem + OFF_WMAX);
            const int cg = tid >> 6, c = tid & 63;
            float m = __int_as_float(0xff800000);
            #pragma unroll
            for (int r = 0; r < 4; r++)
                m = fmaxf(m, wall[(cg * 4 + r) * 64 + c]);
            float bias = ((float*)(smem + OFF_BIAS))[tid];
            float y = fmaxf(m + bias, 0.0f);   // >=0 -> int-bit atomicMax valid
            atomicMax((int*)out + tid, __float_as_int(y));
        }
    }

    // End ticket: last block of this tag resets counters for the next replay.
    if (tid == 0) {
        __threadfence();
        int v = atomicAdd(&g_done[t], 1);
        if (v == (int)gridDim.x - 1) {
            g_done[t] = 0;
            g_count[t] = 0;
        }
    }
}

// ---------------------------------------------------------------------------
// Launch
// ---------------------------------------------------------------------------
extern "C" void kernel_launch(void* const* d_in, const int* in_sizes, int n_in,
                              void* d_out, int out_size) {
    const float* emb = (const float*)d_in[0];
    const float* W   = (const float*)d_in[1];
    const float* b   = (const float*)d_in[2];
    const int*   tag = (const int*)d_in[3];
    // parent/depth irrelevant: root z == elementwise max over all nodes of
    // relu(W[tag] @ emb + b); relu>=0 makes 0 the max identity.

    float* out = (float*)d_out;
    const int N = in_sizes[3];
    const int T = in_sizes[2] / DD;

    static bool attr_set = false;
    if (!attr_set) {
        cudaFuncSetAttribute(gemm_max_kernel,
                             cudaFuncAttributeMaxDynamicSharedMemorySize,
                             SMEM_TOTAL);
        attr_set = true;
    }

    compact_kernel<<<(N + 255) / 256, 256>>>(tag, N, out);

    const int G = 17;  // 17*17 = 289 CTAs <= 296 slots (2/SM): single wave
    dim3 grid(G, T);
    gemm_max_kernel<<<grid, 256, SMEM_TOTAL>>>(emb, W, b, out, G);
}

// round 8
// speedup vs baseline: 2.1526x; 1.0769x over previous
#include <cuda_runtime.h>
#include <cuda_bf16.h>
#include <cstdint>

// Problem constants: D=128, T=17, N=87381
#define DD 128
#define TMAXTAGS 32
#define CAP 87424
#define TILE_M 64

// Scratch (static device globals; zero-initialized at module load)
__device__ int g_count[TMAXTAGS];
__device__ int g_done[TMAXTAGS];
__device__ int g_idx[TMAXTAGS * CAP];

// ---------------------------------------------------------------------------
// PTX helpers (legacy tensor-core path: valid on plain sm_100 target)
// ---------------------------------------------------------------------------
__device__ __forceinline__ uint32_t smem_u32(const void* p) {
    uint32_t a;
    asm("{ .reg .u64 t; cvta.to.shared.u64 t, %1; cvt.u32.u64 %0, t; }"
        : "=r"(a) : "l"(p));
    return a;
}

__device__ __forceinline__ void ldsm_x4(uint32_t* r, uint32_t addr) {
    asm volatile("ldmatrix.sync.aligned.m8n8.x4.shared.b16 {%0,%1,%2,%3}, [%4];"
                 : "=r"(r[0]), "=r"(r[1]), "=r"(r[2]), "=r"(r[3]) : "r"(addr));
}
__device__ __forceinline__ void mma16816(float* d, const uint32_t* a, const uint32_t* b) {
    asm volatile(
        "mma.sync.aligned.m16n8k16.row.col.f32.bf16.bf16.f32 "
        "{%0,%1,%2,%3}, {%4,%5,%6,%7}, {%8,%9}, {%0,%1,%2,%3};"
        : "+f"(d[0]), "+f"(d[1]), "+f"(d[2]), "+f"(d[3])
        : "r"(a[0]), "r"(a[1]), "r"(a[2]), "r"(a[3]), "r"(b[0]), "r"(b[1]));
}

// ---------------------------------------------------------------------------
// Shared memory. Row stride 272B (128 bf16 + 8 pad): every quarter-warp
// ldmatrix phase addresses 8 distinct 16B bank-quads -> conflict-free.
// ---------------------------------------------------------------------------
#define RSTRIDE 272
#define OFF_WHI   0                         // 128*272 = 34816
#define OFF_WLO   34816
#define OFF_AHI   69632                     // 64*272 = 17408
#define OFF_ALO   87040
#define OFF_BIAS  104448                    // 128 f32
#define OFF_WMAX  104960                    // 8 warps * 32 cols f32 = 1024B
#define SMEM_TOTAL 105984

extern __shared__ char s_raw[];

// Convert 4 fp32 -> hi/lo bf16 pairs, store 8B each into padded tiles.
__device__ __forceinline__ void cvt_store(char* hi, char* lo, int row, int lid, float4 v) {
    __nv_bfloat16 h0 = __float2bfloat16(v.x);
    __nv_bfloat16 h1 = __float2bfloat16(v.y);
    __nv_bfloat16 h2 = __float2bfloat16(v.z);
    __nv_bfloat16 h3 = __float2bfloat16(v.w);
    __nv_bfloat16 l0 = __float2bfloat16(v.x - __bfloat162float(h0));
    __nv_bfloat16 l1 = __float2bfloat16(v.y - __bfloat162float(h1));
    __nv_bfloat16 l2 = __float2bfloat16(v.z - __bfloat162float(h2));
    __nv_bfloat16 l3 = __float2bfloat16(v.w - __bfloat162float(h3));
    uint32_t hA = ((uint32_t)__bfloat16_as_ushort(h1) << 16) | __bfloat16_as_ushort(h0);
    uint32_t hB = ((uint32_t)__bfloat16_as_ushort(h3) << 16) | __bfloat16_as_ushort(h2);
    uint32_t lA = ((uint32_t)__bfloat16_as_ushort(l1) << 16) | __bfloat16_as_ushort(l0);
    uint32_t lB = ((uint32_t)__bfloat16_as_ushort(l3) << 16) | __bfloat16_as_ushort(l2);
    uint32_t o = (uint32_t)row * RSTRIDE + (uint32_t)lid * 8;
    *(uint2*)(hi + o) = make_uint2(hA, hB);
    *(uint2*)(lo + o) = make_uint2(lA, lB);
}

// ---------------------------------------------------------------------------
// Kernel 1: zero output (block 0) + bucket node indices by tag.
// ---------------------------------------------------------------------------
__global__ void compact_kernel(const int* __restrict__ tag, int N,
                               float* __restrict__ out) {
    if (blockIdx.x == 0 && threadIdx.x < DD) out[threadIdx.x] = 0.0f;
    int n = blockIdx.x * blockDim.x + threadIdx.x;
    if (n < N) {
        int t = tag[n];
        int p = atomicAdd(&g_count[t], 1);
        g_idx[t * CAP + p] = n;
    }
}

// ---------------------------------------------------------------------------
// Kernel 2: per-tag 3-term split-bf16 HMMA GEMM + max reduce, with a
// register-prefetch pipeline hiding the A-gather DRAM latency under MMAs.
// grid = (G, T), 256 threads, 2 CTAs/SM. Tile = 64 x 128, K=128.
// Warp (rowg = wid&1, colg = wid>>1) owns 32 rows x 32 cols.
// ---------------------------------------------------------------------------
__global__ __launch_bounds__(256, 2) void gemm_max_kernel(
    const float* __restrict__ emb, const float* __restrict__ W,
    const float* __restrict__ b, float* __restrict__ out, int G)
{
    char* smem = s_raw;
    const int t   = blockIdx.y;
    const int tid = threadIdx.x;
    const int wid = tid >> 5;
    const int lid = tid & 31;
    const int cnt = g_count[t];

    const bool active = (long)blockIdx.x * TILE_M < cnt;  // block-uniform
    if (active) {
        const uint32_t sb = smem_u32(smem);
        const int rowg = wid & 1;
        const int colg = wid >> 1;
        const int* idx_t = &g_idx[t * CAP];

        // --- Prefetch tile 0 (warp rows wid, wid+8, ..., wid+56) ---
        float4 pf[8];
        {
            const int base = blockIdx.x * TILE_M;
            #pragma unroll
            for (int i = 0; i < 8; i++) {
                int p = base + wid + i * 8;
                int idx = __ldg(idx_t + min(p, cnt - 1));
                pf[i] = *(const float4*)(emb + (size_t)idx * DD + lid * 4);
            }
        }

        // --- Prologue: convert W[t] into Whi/Wlo (overlaps prefetch), bias ---
        const float* Wt = W + (size_t)t * DD * DD;
        for (int r = wid; r < DD; r += 8) {
            float4 v = *(const float4*)(Wt + r * DD + lid * 4);
            cvt_store(smem + OFF_WHI, smem + OFF_WLO, r, lid, v);
        }
        if (tid < DD) ((float*)(smem + OFF_BIAS))[tid] = b[t * DD + tid];

        // A: base offset for m-frag 0 of this warp's 32 rows
        const uint32_t offA = (uint32_t)(rowg * 32 + (lid & 15)) * RSTRIDE
                            + (uint32_t)(lid >> 4) * 16;
        // B (x4, non-trans): 16 n-rows per ldmatrix (two n-tiles + both k-halves)
        const uint32_t offB = (uint32_t)((lid & 7) + ((lid >> 4) << 3)
                                         + colg * 32) * RSTRIDE
                            + (uint32_t)((lid >> 3) & 1) * 16;

        const uint32_t aHi = sb + OFF_AHI + offA, aLo = sb + OFF_ALO + offA;
        const uint32_t bHi = sb + OFF_WHI + offB, bLo = sb + OFF_WLO + offB;

        float mx[8];
        #pragma unroll
        for (int i = 0; i < 8; i++) mx[i] = __int_as_float(0xff800000);

        for (int tile = blockIdx.x; tile * TILE_M < cnt; tile += G) {
            const int base = tile * TILE_M;

            // Store prefetched rows for THIS tile into A smem
            #pragma unroll
            for (int i = 0; i < 8; i++)
                cvt_store(smem + OFF_AHI, smem + OFF_ALO, wid + i * 8, lid, pf[i]);
            __syncthreads();   // A (and first-iter W) visible to all warps

            // Kick off prefetch for NEXT tile; lands during the mainloop
            {
                const int nbase = (tile + G) * TILE_M;
                if (nbase < cnt) {
                    #pragma unroll
                    for (int i = 0; i < 8; i++) {
                        int p = nbase + wid + i * 8;
                        int idx = __ldg(idx_t + min(p, cnt - 1));
                        pf[i] = *(const float4*)(emb + (size_t)idx * DD + lid * 4);
                    }
                }
            }

            float acc[32];
            #pragma unroll
            for (int i = 0; i < 32; i++) acc[i] = 0.0f;

            // 3-term split GEMM: D += Ahi*Whi + Ahi*Wlo + Alo*Whi
            #pragma unroll
            for (int kk = 0; kk < 8; kk++) {
                uint32_t ah[2][4], al[2][4];
                ldsm_x4(ah[0], aHi + kk * 32);
                ldsm_x4(ah[1], aHi + 16 * RSTRIDE + kk * 32);
                ldsm_x4(al[0], aLo + kk * 32);
                ldsm_x4(al[1], aLo + 16 * RSTRIDE + kk * 32);
                #pragma unroll
                for (int nf2 = 0; nf2 < 2; nf2++) {
                    uint32_t bh[4], bl[4];
                    ldsm_x4(bh, bHi + (uint32_t)nf2 * (16 * RSTRIDE) + kk * 32);
                    ldsm_x4(bl, bLo + (uint32_t)nf2 * (16 * RSTRIDE) + kk * 32);
                    #pragma unroll
                    for (int mf = 0; mf < 2; mf++) {
                        #pragma unroll
                        for (int h = 0; h < 2; h++) {
                            float* a = &acc[(mf * 4 + nf2 * 2 + h) * 4];
                            mma16816(a, ah[mf], bh + h * 2);
                            mma16816(a, ah[mf], bl + h * 2);
                            mma16816(a, al[mf], bh + h * 2);
                        }
                    }
                }
            }

            // Masked per-tile max folded into 8 per-thread column slots
            {
                const int r0 = base + rowg * 32 + (lid >> 2);
                const bool v00 = r0      < cnt, v01 = r0 + 8  < cnt;
                const bool v10 = r0 + 16 < cnt, v11 = r0 + 24 < cnt;
                #pragma unroll
                for (int nf = 0; nf < 4; nf++) {
                    #pragma unroll
                    for (int c = 0; c < 2; c++) {
                        float m = __int_as_float(0xff800000);
                        if (v00) m = fmaxf(m, acc[(0 * 4 + nf) * 4 + c]);
                        if (v01) m = fmaxf(m, acc[(0 * 4 + nf) * 4 + 2 + c]);
                        if (v10) m = fmaxf(m, acc[(1 * 4 + nf) * 4 + c]);
                        if (v11) m = fmaxf(m, acc[(1 * 4 + nf) * 4 + 2 + c]);
                        mx[nf * 2 + c] = fmaxf(mx[nf * 2 + c], m);
                    }
                }
            }
            __syncthreads();   // all A reads done before next tile's stores
        }

        // --- Reduce across lanes sharing the same columns (lid&3 groups) ---
        #pragma unroll
        for (int i = 0; i < 8; i++) {
            float v = mx[i];
            v = fmaxf(v, __shfl_xor_sync(0xFFFFFFFFu, v, 4));
            v = fmaxf(v, __shfl_xor_sync(0xFFFFFFFFu, v, 8));
            v = fmaxf(v, __shfl_xor_sync(0xFFFFFFFFu, v, 16));
            mx[i] = v;
        }
        float* wm = (float*)(smem + OFF_WMAX);
        if (lid < 4) {
            #pragma unroll
            for (int nf = 0; nf < 4; nf++) {
                wm[wid * 32 + nf * 8 + lid * 2 + 0] = mx[nf * 2 + 0];
                wm[wid * 32 + nf * 8 + lid * 2 + 1] = mx[nf * 2 + 1];
            }
        }
        __syncthreads();

        if (tid < DD) {
            const int cg = tid >> 5, cc = tid & 31;
            float m = fmaxf(wm[(cg * 2 + 0) * 32 + cc],
                            wm[(cg * 2 + 1) * 32 + cc]);
            float bias = ((float*)(smem + OFF_BIAS))[tid];
            float y = fmaxf(m + bias, 0.0f);   // >=0 -> int-bit atomicMax valid
            atomicMax((int*)out + tid, __float_as_int(y));
        }
    }

    // End ticket: last block of this tag resets counters for the next replay.
    if (tid == 0) {
        __threadfence();
        int v = atomicAdd(&g_done[t], 1);
        if (v == (int)gridDim.x - 1) {
            g_done[t] = 0;
            g_count[t] = 0;
        }
    }
}

// ---------------------------------------------------------------------------
// Launch
// ---------------------------------------------------------------------------
extern "C" void kernel_launch(void* const* d_in, const int* in_sizes, int n_in,
                              void* d_out, int out_size) {
    const float* emb = (const float*)d_in[0];
    const float* W   = (const float*)d_in[1];
    const float* b   = (const float*)d_in[2];
    const int*   tag = (const int*)d_in[3];
    // parent/depth irrelevant: root z == elementwise max over all nodes of
    // relu(W[tag] @ emb + b); relu>=0 makes 0 the max identity.

    float* out = (float*)d_out;
    const int N = in_sizes[3];
    const int T = in_sizes[2] / DD;

    static bool attr_set = false;
    if (!attr_set) {
        cudaFuncSetAttribute(gemm_max_kernel,
                             cudaFuncAttributeMaxDynamicSharedMemorySize,
                             SMEM_TOTAL);
        attr_set = true;
    }

    compact_kernel<<<(N + 255) / 256, 256>>>(tag, N, out);

    const int G = 17;  // 17*17 = 289 CTAs <= 296 slots (2/SM): single wave
    dim3 grid(G, T);
    gemm_max_kernel<<<grid, 256, SMEM_TOTAL>>>(emb, W, b, out, G);
}

// round 9
// speedup vs baseline: 3.9169x; 1.8197x over previous
#include <cuda_runtime.h>
#include <cuda_fp16.h>
#include <cstdint>

// Problem constants: D=128, T=17, N=87381
#define DD 128
#define TMAXTAGS 32
#define CAP 87424
#define TILE_M 64

// Scratch (static device globals; zero-initialized at module load)
__device__ int g_count[TMAXTAGS];
__device__ int g_done[TMAXTAGS];
__device__ int g_idx[TMAXTAGS * CAP];

// ---------------------------------------------------------------------------
// PTX helpers (legacy tensor-core path: valid on plain sm_100 target)
// ---------------------------------------------------------------------------
__device__ __forceinline__ uint32_t smem_u32(const void* p) {
    uint32_t a;
    asm("{ .reg .u64 t; cvta.to.shared.u64 t, %1; cvt.u32.u64 %0, t; }"
        : "=r"(a) : "l"(p));
    return a;
}

__device__ __forceinline__ void ldsm_x4(uint32_t* r, uint32_t addr) {
    asm volatile("ldmatrix.sync.aligned.m8n8.x4.shared.b16 {%0,%1,%2,%3}, [%4];"
                 : "=r"(r[0]), "=r"(r[1]), "=r"(r[2]), "=r"(r[3]) : "r"(addr));
}
__device__ __forceinline__ void mma16816(float* d, const uint32_t* a, const uint32_t* b) {
    asm volatile(
        "mma.sync.aligned.m16n8k16.row.col.f32.f16.f16.f32 "
        "{%0,%1,%2,%3}, {%4,%5,%6,%7}, {%8,%9}, {%0,%1,%2,%3};"
        : "+f"(d[0]), "+f"(d[1]), "+f"(d[2]), "+f"(d[3])
        : "r"(a[0]), "r"(a[1]), "r"(a[2]), "r"(a[3]), "r"(b[0]), "r"(b[1]));
}

// ---------------------------------------------------------------------------
// Shared memory. Row stride 272B (128 fp16 + 8 pad): every quarter-warp
// ldmatrix phase addresses 8 distinct 16B bank-quads -> conflict-free.
// ---------------------------------------------------------------------------
#define RSTRIDE 272
#define OFF_WHI   0                         // 128*272 = 34816
#define OFF_WLO   34816
#define OFF_A     69632                     // 64*272 = 17408
#define OFF_BIAS  87040                     // 128 f32
#define OFF_WMAX  87552                     // 8 warps * 32 cols f32 = 1024B
#define SMEM_TOTAL 88576

extern __shared__ char s_raw[];

// Convert float4 -> 4 fp16, store 8B into padded tile (single-precision tile).
__device__ __forceinline__ void cvt_store1(char* dst, int row, int lid, float4 v) {
    __half2 p0 = __floats2half2_rn(v.x, v.y);
    __half2 p1 = __floats2half2_rn(v.z, v.w);
    uint32_t o = (uint32_t)row * RSTRIDE + (uint32_t)lid * 8;
    *(uint2*)(dst + o) = make_uint2(*(uint32_t*)&p0, *(uint32_t*)&p1);
}

// Convert float4 -> hi/lo fp16 pairs (22-bit effective), store 8B each.
__device__ __forceinline__ void cvt_store2(char* hi, char* lo, int row, int lid, float4 v) {
    __half h0 = __float2half_rn(v.x), h1 = __float2half_rn(v.y);
    __half h2 = __float2half_rn(v.z), h3 = __float2half_rn(v.w);
    __half l0 = __float2half_rn(v.x - __half2float(h0));
    __half l1 = __float2half_rn(v.y - __half2float(h1));
    __half l2 = __float2half_rn(v.z - __half2float(h2));
    __half l3 = __float2half_rn(v.w - __half2float(h3));
    uint32_t hA = ((uint32_t)__half_as_ushort(h1) << 16) | __half_as_ushort(h0);
    uint32_t hB = ((uint32_t)__half_as_ushort(h3) << 16) | __half_as_ushort(h2);
    uint32_t lA = ((uint32_t)__half_as_ushort(l1) << 16) | __half_as_ushort(l0);
    uint32_t lB = ((uint32_t)__half_as_ushort(l3) << 16) | __half_as_ushort(l2);
    uint32_t o = (uint32_t)row * RSTRIDE + (uint32_t)lid * 8;
    *(uint2*)(hi + o) = make_uint2(hA, hB);
    *(uint2*)(lo + o) = make_uint2(lA, lB);
}

// ---------------------------------------------------------------------------
// Kernel 1: zero output + block-aggregated bucketing (17 global atomics per
// block instead of one per node; kills the 17-address L2 contention).
// ---------------------------------------------------------------------------
__global__ void compact_kernel(const int* __restrict__ tag, int N,
                               float* __restrict__ out) {
    __shared__ int s_cnt[TMAXTAGS];
    __shared__ int s_base[TMAXTAGS];
    const int tid = threadIdx.x;
    if (blockIdx.x == 0 && tid < DD) out[tid] = 0.0f;
    if (tid < TMAXTAGS) s_cnt[tid] = 0;
    __syncthreads();

    const int n = blockIdx.x * blockDim.x + tid;
    int t = 0, p = 0;
    if (n < N) {
        t = tag[n];
        p = atomicAdd(&s_cnt[t], 1);
    }
    __syncthreads();
    if (tid < TMAXTAGS && s_cnt[tid] > 0)
        s_base[tid] = atomicAdd(&g_count[tid], s_cnt[tid]);
    __syncthreads();
    if (n < N) g_idx[t * CAP + s_base[t] + p] = n;
}

// ---------------------------------------------------------------------------
// Kernel 2: per-tag 2-term fp16 HMMA GEMM + max reduce, register-prefetch
// pipeline hiding the A-gather DRAM latency under MMAs.
// D = A_fp16 @ (Whi + Wlo)^T : A at 11 mantissa bits, W at 22 -> rel ~4e-5.
// grid = (G, T), 256 threads, 2 CTAs/SM. Tile = 64 x 128, K=128.
// Warp (rowg = wid&1, colg = wid>>1) owns 32 rows x 32 cols.
// ---------------------------------------------------------------------------
__global__ __launch_bounds__(256, 2) void gemm_max_kernel(
    const float* __restrict__ emb, const float* __restrict__ W,
    const float* __restrict__ b, float* __restrict__ out, int G)
{
    char* smem = s_raw;
    const int t   = blockIdx.y;
    const int tid = threadIdx.x;
    const int wid = tid >> 5;
    const int lid = tid & 31;
    const int cnt = g_count[t];

    const bool active = (long)blockIdx.x * TILE_M < cnt;  // block-uniform
    if (active) {
        const uint32_t sb = smem_u32(smem);
        const int rowg = wid & 1;
        const int colg = wid >> 1;
        const int* idx_t = &g_idx[t * CAP];

        // --- Prefetch tile 0 (warp rows wid, wid+8, ..., wid+56) ---
        float4 pf[8];
        {
            const int base = blockIdx.x * TILE_M;
            #pragma unroll
            for (int i = 0; i < 8; i++) {
                int p = base + wid + i * 8;
                int idx = __ldg(idx_t + min(p, cnt - 1));
                pf[i] = *(const float4*)(emb + (size_t)idx * DD + lid * 4);
            }
        }

        // --- Prologue: convert W[t] into Whi/Wlo (overlaps prefetch), bias ---
        const float* Wt = W + (size_t)t * DD * DD;
        for (int r = wid; r < DD; r += 8) {
            float4 v = *(const float4*)(Wt + r * DD + lid * 4);
            cvt_store2(smem + OFF_WHI, smem + OFF_WLO, r, lid, v);
        }
        if (tid < DD) ((float*)(smem + OFF_BIAS))[tid] = b[t * DD + tid];

        // A: base offset for m-frag 0 of this warp's 32 rows
        const uint32_t offA = (uint32_t)(rowg * 32 + (lid & 15)) * RSTRIDE
                            + (uint32_t)(lid >> 4) * 16;
        // B (x4, non-trans): 16 n-rows per ldmatrix (two n-tiles, both k-halves)
        const uint32_t offB = (uint32_t)((lid & 7) + ((lid >> 4) << 3)
                                         + colg * 32) * RSTRIDE
                            + (uint32_t)((lid >> 3) & 1) * 16;

        const uint32_t aT  = sb + OFF_A   + offA;
        const uint32_t bHi = sb + OFF_WHI + offB, bLo = sb + OFF_WLO + offB;

        float mx[8];
        #pragma unroll
        for (int i = 0; i < 8; i++) mx[i] = __int_as_float(0xff800000);

        for (int tile = blockIdx.x; tile * TILE_M < cnt; tile += G) {
            const int base = tile * TILE_M;

            // Store prefetched rows for THIS tile into A smem (fp16 single)
            #pragma unroll
            for (int i = 0; i < 8; i++)
                cvt_store1(smem + OFF_A, wid + i * 8, lid, pf[i]);
            __syncthreads();   // A (and first-iter W) visible to all warps

            // Kick off prefetch for NEXT tile; lands during the mainloop
            {
                const int nbase = (tile + G) * TILE_M;
                if (nbase < cnt) {
                    #pragma unroll
                    for (int i = 0; i < 8; i++) {
                        int p = nbase + wid + i * 8;
                        int idx = __ldg(idx_t + min(p, cnt - 1));
                        pf[i] = *(const float4*)(emb + (size_t)idx * DD + lid * 4);
                    }
                }
            }

            float acc[32];
            #pragma unroll
            for (int i = 0; i < 32; i++) acc[i] = 0.0f;

            // 2-term GEMM: D += A*Whi + A*Wlo
            #pragma unroll
            for (int kk = 0; kk < 8; kk++) {
                uint32_t a[2][4];
                ldsm_x4(a[0], aT + kk * 32);
                ldsm_x4(a[1], aT + 16 * RSTRIDE + kk * 32);
                #pragma unroll
                for (int nf2 = 0; nf2 < 2; nf2++) {
                    uint32_t bh[4], bl[4];
                    ldsm_x4(bh, bHi + (uint32_t)nf2 * (16 * RSTRIDE) + kk * 32);
                    ldsm_x4(bl, bLo + (uint32_t)nf2 * (16 * RSTRIDE) + kk * 32);
                    #pragma unroll
                    for (int mf = 0; mf < 2; mf++) {
                        #pragma unroll
                        for (int h = 0; h < 2; h++) {
                            float* d = &acc[(mf * 4 + nf2 * 2 + h) * 4];
                            mma16816(d, a[mf], bh + h * 2);
                            mma16816(d, a[mf], bl + h * 2);
                        }
                    }
                }
            }

            // Masked per-tile max folded into 8 per-thread column slots
            {
                const int r0 = base + rowg * 32 + (lid >> 2);
                const bool v00 = r0      < cnt, v01 = r0 + 8  < cnt;
                const bool v10 = r0 + 16 < cnt, v11 = r0 + 24 < cnt;
                #pragma unroll
                for (int nf = 0; nf < 4; nf++) {
                    #pragma unroll
                    for (int c = 0; c < 2; c++) {
                        float m = __int_as_float(0xff800000);
                        if (v00) m = fmaxf(m, acc[(0 * 4 + nf) * 4 + c]);
                        if (v01) m = fmaxf(m, acc[(0 * 4 + nf) * 4 + 2 + c]);
                        if (v10) m = fmaxf(m, acc[(1 * 4 + nf) * 4 + c]);
                        if (v11) m = fmaxf(m, acc[(1 * 4 + nf) * 4 + 2 + c]);
                        mx[nf * 2 + c] = fmaxf(mx[nf * 2 + c], m);
                    }
                }
            }
            __syncthreads();   // all A reads done before next tile's stores
        }

        // --- Reduce across lanes sharing the same columns (lid&3 groups) ---
        #pragma unroll
        for (int i = 0; i < 8; i++) {
            float v = mx[i];
            v = fmaxf(v, __shfl_xor_sync(0xFFFFFFFFu, v, 4));
            v = fmaxf(v, __shfl_xor_sync(0xFFFFFFFFu, v, 8));
            v = fmaxf(v, __shfl_xor_sync(0xFFFFFFFFu, v, 16));
            mx[i] = v;
        }
        float* wm = (float*)(smem + OFF_WMAX);
        if (lid < 4) {
            #pragma unroll
            for (int nf = 0; nf < 4; nf++) {
                wm[wid * 32 + nf * 8 + lid * 2 + 0] = mx[nf * 2 + 0];
                wm[wid * 32 + nf * 8 + lid * 2 + 1] = mx[nf * 2 + 1];
            }
        }
        __syncthreads();

        if (tid < DD) {
            const int cg = tid >> 5, cc = tid & 31;
            float m = fmaxf(wm[(cg * 2 + 0) * 32 + cc],
                            wm[(cg * 2 + 1) * 32 + cc]);
            float bias = ((float*)(smem + OFF_BIAS))[tid];
            float y = fmaxf(m + bias, 0.0f);   // >=0 -> int-bit atomicMax valid
            atomicMax((int*)out + tid, __float_as_int(y));
        }
    }

    // End ticket: last block of this tag resets counters for the next replay.
    if (tid == 0) {
        __threadfence();
        int v = atomicAdd(&g_done[t], 1);
        if (v == (int)gridDim.x - 1) {
            g_done[t] = 0;
            g_count[t] = 0;
        }
    }
}

// ---------------------------------------------------------------------------
// Launch
// ---------------------------------------------------------------------------
extern "C" void kernel_launch(void* const* d_in, const int* in_sizes, int n_in,
                              void* d_out, int out_size) {
    const float* emb = (const float*)d_in[0];
    const float* W   = (const float*)d_in[1];
    const float* b   = (const float*)d_in[2];
    const int*   tag = (const int*)d_in[3];
    // parent/depth irrelevant: root z == elementwise max over all nodes of
    // relu(W[tag] @ emb + b); relu>=0 makes 0 the max identity.

    float* out = (float*)d_out;
    const int N = in_sizes[3];
    const int T = in_sizes[2] / DD;

    static bool attr_set = false;
    if (!attr_set) {
        cudaFuncSetAttribute(gemm_max_kernel,
                             cudaFuncAttributeMaxDynamicSharedMemorySize,
                             SMEM_TOTAL);
        attr_set = true;
    }

    compact_kernel<<<(N + 511) / 512, 512>>>(tag, N, out);

    const int G = 17;  // 17*17 = 289 CTAs <= 296 slots (2/SM): single wave
    dim3 grid(G, T);
    gemm_max_kernel<<<grid, 256, SMEM_TOTAL>>>(emb, W, b, out, G);
}